// round 16
// baseline (speedup 1.0000x reference)
#include <cuda_runtime.h>
#include <cuda_fp16.h>
#include <math.h>
#include <stdint.h>

// Problem constants
#define NMAX 50000
#define EMAX 300000
#define INDIM 128
#define HID 64
#define HEADS 4
#define QKVDIM 256
#define COLS_ALL 832    // Wq|Wk|Wv|Wskip
#define OUTD 64
#define NTILES 13

// ---------------- scratch ----------------
__device__ float g_ball[COLS_ALL];
__device__ __align__(16) __half g_Wt_h[COLS_ALL * INDIM];      // [n][k] fp16
__device__ __align__(16) __half g_qh[(size_t)NMAX * QKVDIM];   // q fp16
__device__ __align__(16) __half g_kvh[(size_t)NMAX * 512];     // k[256] | v[256] fp16
__device__ __align__(16) __half g_skiph[(size_t)NMAX * HID];   // skip fp16
__device__ float g_Wms[HID * OUTD];
__device__ int g_deg[NMAX];
__device__ int g_cursor[NMAX];
__device__ int g_rowstart[NMAX + 1];
__device__ int g_esrc[EMAX];
__device__ int g_bsum[4096];

// ---------------- helpers ----------------
__device__ __forceinline__ uint32_t smem_u32(const void* p) {
    uint32_t a;
    asm("{ .reg .u64 t; cvta.to.shared.u64 t, %1; cvt.u32.u64 %0, t; }" : "=r"(a) : "l"(p));
    return a;
}

#define LDMX4(r0, r1, r2, r3, addr) \
    asm volatile("ldmatrix.sync.aligned.m8n8.x4.shared.b16 {%0,%1,%2,%3}, [%4];" \
                 : "=r"(r0), "=r"(r1), "=r"(r2), "=r"(r3) : "r"(addr))

#define MMA16816H(d, a, b0, b1) \
    asm volatile("mma.sync.aligned.m16n8k16.row.col.f32.f16.f16.f32 " \
                 "{%0,%1,%2,%3},{%4,%5,%6,%7},{%8,%9},{%0,%1,%2,%3};" \
                 : "+f"((d)[0]), "+f"((d)[1]), "+f"((d)[2]), "+f"((d)[3]) \
                 : "r"((a)[0]), "r"((a)[1]), "r"((a)[2]), "r"((a)[3]), "r"(b0), "r"(b1))

__device__ __forceinline__ uint32_t h2u(__half2 h) { return *reinterpret_cast<uint32_t*>(&h); }

// ---------------- prep: coalesced tiled transpose W -> g_Wt_h (fp16) + biases ----------------
__global__ void prep_kernel(const float* __restrict__ Wq, const float* __restrict__ bq,
                            const float* __restrict__ Wk, const float* __restrict__ bk,
                            const float* __restrict__ Wv, const float* __restrict__ bv,
                            const float* __restrict__ Ws, const float* __restrict__ bs) {
    __shared__ __half tile[32][33];
    int n0 = blockIdx.x * 32;
    int k0 = blockIdx.y * 32;
    int tx = threadIdx.x, ty = threadIdx.y;

#pragma unroll
    for (int r = ty; r < 32; r += 8) {
        int k = k0 + r;
        int n = n0 + tx;
        float w = (n < 256) ? Wq[k * 256 + n]
                : (n < 512) ? Wk[k * 256 + (n - 256)]
                : (n < 768) ? Wv[k * 256 + (n - 512)]
                :             Ws[k * 64  + (n - 768)];
        tile[r][tx] = __float2half_rn(w);
    }
    if (blockIdx.y == 0 && ty == 0) {
        int n = n0 + tx;
        g_ball[n] = (n < 256) ? bq[n] : (n < 512) ? bk[n - 256]
                  : (n < 768) ? bv[n - 512] : bs[n - 768];
    }
    __syncthreads();
#pragma unroll
    for (int r = ty; r < 32; r += 8) {
        int n = n0 + r;
        int k = k0 + tx;
        g_Wt_h[(size_t)n * INDIM + k] = tile[tx][r];
    }
}

// ---------------- spectral norm power iteration (warp-level) ----------------
__global__ void sigma_kernel(const float* __restrict__ Wmlp) {
    __shared__ float Wsh[64 * 65];
    __shared__ float ush[64], vsh[64];
    int t = threadIdx.x;  // 32 threads
    for (int i = t; i < 4096; i += 32) {
        int r = i >> 6, c = i & 63;
        Wsh[r * 65 + c] = Wmlp[i];
    }
    ush[t] = 0.125f; ush[t + 32] = 0.125f;
    __syncwarp();
    float up0 = 0.f, up1 = 0.f;
    for (int it = 0; it < 20; ++it) {
        float s0 = 0.f, s1 = 0.f;
        for (int i = 0; i < 64; ++i) {
            float ui = ush[i];
            s0 += Wsh[i * 65 + t] * ui;
            s1 += Wsh[i * 65 + t + 32] * ui;
        }
        float nn = s0 * s0 + s1 * s1;
#pragma unroll
        for (int o = 16; o > 0; o >>= 1) nn += __shfl_xor_sync(0xFFFFFFFFu, nn, o);
        float inv = 1.f / (sqrtf(nn) + 1e-12f);
        vsh[t] = s0 * inv; vsh[t + 32] = s1 * inv;
        __syncwarp();
        float r0 = 0.f, r1 = 0.f;
        for (int j = 0; j < 64; ++j) {
            float vj = vsh[j];
            r0 += Wsh[t * 65 + j] * vj;
            r1 += Wsh[(t + 32) * 65 + j] * vj;
        }
        up0 = r0; up1 = r1;
        float nu = r0 * r0 + r1 * r1;
#pragma unroll
        for (int o = 16; o > 0; o >>= 1) nu += __shfl_xor_sync(0xFFFFFFFFu, nu, o);
        float invu = 1.f / (sqrtf(nu) + 1e-12f);
        ush[t] = r0 * invu; ush[t + 32] = r1 * invu;
        __syncwarp();
    }
    float sg = ush[t] * up0 + ush[t + 32] * up1;
#pragma unroll
    for (int o = 16; o > 0; o >>= 1) sg += __shfl_xor_sync(0xFFFFFFFFu, sg, o);
    float rinv = 1.f / sg;
    for (int i = t; i < 4096; i += 32) {
        int r = i >> 6, c = i & 63;
        g_Wms[i] = Wsh[r * 65 + c] * rinv;
    }
}

// ---------------- CSR build ----------------
__global__ void zero_kernel(int n) {
    int i = blockIdx.x * blockDim.x + threadIdx.x;
    if (i < n) { g_deg[i] = 0; g_cursor[i] = 0; }
}
__global__ void hist_kernel(const int* __restrict__ ei, int E) {
    int e = blockIdx.x * blockDim.x + threadIdx.x;
    if (e < E) atomicAdd(&g_deg[ei[E + e]], 1);
}
__global__ void scan_part1(int n) {
    __shared__ int s[256];
    int t = threadIdx.x;
    int i = blockIdx.x * 256 + t;
    s[t] = (i < n) ? g_deg[i] : 0;
    __syncthreads();
#pragma unroll
    for (int o = 128; o > 0; o >>= 1) {
        if (t < o) s[t] += s[t + o];
        __syncthreads();
    }
    if (t == 0) g_bsum[blockIdx.x] = s[0];
}
__global__ void scan_part2(int nblk, int n) {
    __shared__ int s[256];
    int t = threadIdx.x;
    s[t] = (t < nblk) ? g_bsum[t] : 0;
    __syncthreads();
#pragma unroll
    for (int o = 1; o < 256; o <<= 1) {
        int v = (t >= o) ? s[t - o] : 0;
        __syncthreads();
        s[t] += v;
        __syncthreads();
    }
    if (t < nblk) g_bsum[t] = (t == 0) ? 0 : s[t - 1];
    if (t == nblk - 1) g_rowstart[n] = s[t];
}
__global__ void scan_part3(int n) {
    __shared__ int s[256];
    int t = threadIdx.x;
    int i = blockIdx.x * 256 + t;
    int v = (i < n) ? g_deg[i] : 0;
    s[t] = v;
    __syncthreads();
#pragma unroll
    for (int o = 1; o < 256; o <<= 1) {
        int u = (t >= o) ? s[t - o] : 0;
        __syncthreads();
        s[t] += u;
        __syncthreads();
    }
    if (i < n) g_rowstart[i] = g_bsum[blockIdx.x] + s[t] - v;
}
__global__ void scatter_edges_kernel(const int* __restrict__ ei, int E) {
    int e = blockIdx.x * blockDim.x + threadIdx.x;
    if (e >= E) return;
    int dst = ei[E + e];
    int pos = g_rowstart[dst] + atomicAdd(&g_cursor[dst], 1);
    g_esrc[pos] = ei[e];
}

// ---------------- fp16 single-pass mma.sync projection GEMM (double-buffered B) ----------------
// smem: A 34816 + 2x B 17408 = 69632 B -> 3 CTAs/SM (grid avg residency 2.64, no loss).
#define LDA_B 272
#define SM_A 0
#define SM_B0 34816
#define SM_B1 52224
#define GEMM_SMEM_BYTES 69632

__global__ void __launch_bounds__(256, 3) gemm_mma_kernel(const float* __restrict__ x, int nrows) {
    extern __shared__ __align__(16) char sm[];
    const uint32_t s_base = smem_u32(sm);

    int tid = threadIdx.x;
    int lane = tid & 31;
    int wid = tid >> 5;
    int wm = wid & 3;
    int wn = wid >> 2;
    int row0 = blockIdx.x * 128;

    // B fill helper (nb tile -> smem offset)
    auto fillB = [&](int nb, uint32_t smoff) {
        int col0 = nb * 64;
#pragma unroll
        for (int p = 0; p < 4; ++p) {
            int idx = tid + p * 256;
            int row = idx >> 4;
            int c8 = idx & 15;
            size_t gb = ((size_t)(col0 + row) * INDIM + c8 * 8);
            uint4 vh = *reinterpret_cast<const uint4*>(&g_Wt_h[gb]);
            uint32_t off = (uint32_t)row * LDA_B + (uint32_t)c8 * 16;
            *reinterpret_cast<uint4*>(sm + smoff + off) = vh;
        }
    };

    // ---- A fill: fp32 -> fp16 (once) ----
    {
#pragma unroll
        for (int p = 0; p < 16; ++p) {
            int idx = tid + p * 256;
            int row = idx >> 5;
            int c4 = idx & 31;
            int gr = row0 + row;
            float4 v = make_float4(0.f, 0.f, 0.f, 0.f);
            if (gr < nrows) v = *reinterpret_cast<const float4*>(x + (size_t)gr * INDIM + c4 * 4);
            uint32_t hp0 = h2u(__floats2half2_rn(v.x, v.y));
            uint32_t hp1 = h2u(__floats2half2_rn(v.z, v.w));
            uint32_t off = (uint32_t)row * LDA_B + (uint32_t)c4 * 8;
            *reinterpret_cast<uint2*>(sm + SM_A + off) = make_uint2(hp0, hp1);
        }
    }
    fillB(0, SM_B0);
    __syncthreads();

    int ar = lane & 15, ac8 = lane >> 4;
    int bg = lane >> 3;
    int bn = ((bg >> 1) << 3) + (lane & 7);
    int bk8 = bg & 1;
    uint32_t a_lane_off = (uint32_t)(wm * 32 + ar) * LDA_B + (uint32_t)ac8 * 16;
    uint32_t b_lane_off = (uint32_t)(wn * 32 + bn) * LDA_B + (uint32_t)bk8 * 16;

    for (int nb = 0; nb < NTILES; ++nb) {
        int col0 = nb * 64;
        int sel = nb >> 2;                       // 0=q 1=k 2=v 3=skip
        uint32_t curB = (nb & 1) ? SM_B1 : SM_B0;
        uint32_t nxtB = (nb & 1) ? SM_B0 : SM_B1;

        // prefetch next tile's B into the other buffer (overlaps with MMA below)
        if (nb + 1 < NTILES) fillB(nb + 1, nxtB);

        float acc[2][4][4];
#pragma unroll
        for (int mb = 0; mb < 2; ++mb)
#pragma unroll
            for (int jn = 0; jn < 4; ++jn)
#pragma unroll
                for (int r = 0; r < 4; ++r) acc[mb][jn][r] = 0.f;

#pragma unroll 2
        for (int kk = 0; kk < 8; ++kk) {
            uint32_t kbyte = (uint32_t)kk * 32;
            uint32_t ah[8], bb[8];
            uint32_t aaddr0 = s_base + SM_A + a_lane_off + kbyte;
            LDMX4(ah[0], ah[1], ah[2], ah[3], aaddr0);
            LDMX4(ah[4], ah[5], ah[6], ah[7], aaddr0 + 16 * LDA_B);
            uint32_t baddr0 = s_base + curB + b_lane_off + kbyte;
            LDMX4(bb[0], bb[1], bb[2], bb[3], baddr0);
            LDMX4(bb[4], bb[5], bb[6], bb[7], baddr0 + 16 * LDA_B);
#pragma unroll
            for (int mb = 0; mb < 2; ++mb) {
#pragma unroll
                for (int jn = 0; jn < 4; ++jn) {
                    MMA16816H(acc[mb][jn], &ah[mb * 4], bb[jn * 2], bb[jn * 2 + 1]);
                }
            }
        }

        int g = lane >> 2, t2 = (lane & 3) * 2;
#pragma unroll
        for (int mb = 0; mb < 2; ++mb) {
            int gr0 = row0 + wm * 32 + mb * 16 + g;
#pragma unroll
            for (int jn = 0; jn < 4; ++jn) {
                int gc = col0 + wn * 32 + jn * 8 + t2;
                float b0 = g_ball[gc], b1 = g_ball[gc + 1];
                float v00 = acc[mb][jn][0] + b0, v01 = acc[mb][jn][1] + b1;
                float v10 = acc[mb][jn][2] + b0, v11 = acc[mb][jn][3] + b1;
                if (sel == 0) {
                    if (gr0 < nrows)
                        *reinterpret_cast<__half2*>(&g_qh[(size_t)gr0 * QKVDIM + gc]) = __floats2half2_rn(v00, v01);
                    if (gr0 + 8 < nrows)
                        *reinterpret_cast<__half2*>(&g_qh[(size_t)(gr0 + 8) * QKVDIM + gc]) = __floats2half2_rn(v10, v11);
                } else if (sel == 3) {
                    int sc = gc - 768;
                    if (gr0 < nrows)
                        *reinterpret_cast<__half2*>(&g_skiph[(size_t)gr0 * HID + sc]) = __floats2half2_rn(v00, v01);
                    if (gr0 + 8 < nrows)
                        *reinterpret_cast<__half2*>(&g_skiph[(size_t)(gr0 + 8) * HID + sc]) = __floats2half2_rn(v10, v11);
                } else {
                    int koff = gc - 256;   // k: [0,256)  v: [256,512)
                    if (gr0 < nrows)
                        *reinterpret_cast<__half2*>(&g_kvh[(size_t)gr0 * 512 + koff]) = __floats2half2_rn(v00, v01);
                    if (gr0 + 8 < nrows)
                        *reinterpret_cast<__half2*>(&g_kvh[(size_t)(gr0 + 8) * 512 + koff]) = __floats2half2_rn(v10, v11);
                }
            }
        }
        __syncthreads();  // fill of nxtB complete + curB reads done before refill
    }
}

// ---------------- fused attention + head mean + skip + tanh + MLP ----------------
// Warp per node; predicated 4-edge batches + next-batch index prefetch.
__global__ void __launch_bounds__(256) attn_kernel(float* __restrict__ out, int n, int ngroups) {
    __shared__ float Wsm[64 * 66];
    __shared__ float hsm[8][64];
    int tid = threadIdx.x;
    int lane = tid & 31;
    int w = tid >> 5;

    for (int i = tid; i < 4096; i += 256) Wsm[(i >> 6) * 66 + (i & 63)] = g_Wms[i];
    __syncthreads();

    for (int grp = blockIdx.x; grp < ngroups; grp += gridDim.x) {
        int gw = grp * 8 + w;
        bool valid = gw < n;

        if (valid) {
            uint4 qv = *reinterpret_cast<const uint4*>(g_qh + (size_t)gw * QKVDIM + lane * 8);
            float2 q0 = __half22float2(*reinterpret_cast<__half2*>(&qv.x));
            float2 q1 = __half22float2(*reinterpret_cast<__half2*>(&qv.y));
            float2 q2 = __half22float2(*reinterpret_cast<__half2*>(&qv.z));
            float2 q3 = __half22float2(*reinterpret_cast<__half2*>(&qv.w));

            int start = g_rowstart[gw], end = g_rowstart[gw + 1];
            float S[8] = {0.f, 0.f, 0.f, 0.f, 0.f, 0.f, 0.f, 0.f};
            float d = 0.f;

            // prefetch first batch's indices
            int idxN[4];
            if (start < end) {
                int rem0 = end - start;
#pragma unroll
                for (int i = 0; i < 4; ++i) idxN[i] = g_esrc[(i < rem0) ? (start + i) : start];
            }

            for (int p = start; p < end; p += 4) {
                int rem = end - p;  // >= 1
                int idx[4];
#pragma unroll
                for (int i = 0; i < 4; ++i) idx[i] = idxN[i];
                // prefetch next batch's indices (overlaps with kv gather below)
                int pn = p + 4;
                if (pn < end) {
                    int remn = end - pn;
#pragma unroll
                    for (int i = 0; i < 4; ++i) idxN[i] = g_esrc[(i < remn) ? (pn + i) : pn];
                }

                uint4 kk[4], vv[4];
#pragma unroll
                for (int i = 0; i < 4; ++i) {
                    const uint4* kv = reinterpret_cast<const uint4*>(g_kvh + (size_t)idx[i] * 512);
                    kk[i] = kv[lane];
                    vv[i] = kv[lane + 32];
                }
                float t[4];
#pragma unroll
                for (int i = 0; i < 4; ++i) {
                    float2 k0 = __half22float2(*reinterpret_cast<__half2*>(&kk[i].x));
                    float2 k1 = __half22float2(*reinterpret_cast<__half2*>(&kk[i].y));
                    float2 k2 = __half22float2(*reinterpret_cast<__half2*>(&kk[i].z));
                    float2 k3 = __half22float2(*reinterpret_cast<__half2*>(&kk[i].w));
                    t[i] = q0.x * k0.x + q0.y * k0.y + q1.x * k1.x + q1.y * k1.y
                         + q2.x * k2.x + q2.y * k2.y + q3.x * k3.x + q3.y * k3.y;
                }
#pragma unroll
                for (int i = 0; i < 4; ++i) t[i] += __shfl_xor_sync(0xFFFFFFFFu, t[i], 1);
#pragma unroll
                for (int i = 0; i < 4; ++i) t[i] += __shfl_xor_sync(0xFFFFFFFFu, t[i], 2);
#pragma unroll
                for (int i = 0; i < 4; ++i) t[i] += __shfl_xor_sync(0xFFFFFFFFu, t[i], 4);
                float e[4];
#pragma unroll
                for (int i = 0; i < 4; ++i) {
                    e[i] = (i < rem) ? __expf(t[i] * 0.125f) : 0.f;
                    d += e[i];
                }
#pragma unroll
                for (int i = 0; i < 4; ++i) {
                    float2 v0 = __half22float2(*reinterpret_cast<__half2*>(&vv[i].x));
                    float2 v1 = __half22float2(*reinterpret_cast<__half2*>(&vv[i].y));
                    float2 v2 = __half22float2(*reinterpret_cast<__half2*>(&vv[i].z));
                    float2 v3 = __half22float2(*reinterpret_cast<__half2*>(&vv[i].w));
                    S[0] += e[i] * v0.x; S[1] += e[i] * v0.y;
                    S[2] += e[i] * v1.x; S[3] += e[i] * v1.y;
                    S[4] += e[i] * v2.x; S[5] += e[i] * v2.y;
                    S[6] += e[i] * v3.x; S[7] += e[i] * v3.y;
                }
            }

            float r = 1.f / (d + 1e-16f);
#pragma unroll
            for (int j = 0; j < 8; ++j) {
                float s = S[j] * r;
                s += __shfl_xor_sync(0xFFFFFFFFu, s, 8);
                s += __shfl_xor_sync(0xFFFFFFFFu, s, 16);
                S[j] = s;
            }

            if (lane < 8) {
                const __half* sk = g_skiph + (size_t)gw * HID + lane * 8;
#pragma unroll
                for (int j = 0; j < 8; ++j)
                    hsm[w][lane * 8 + j] = tanhf(0.25f * S[j] + __half2float(sk[j]));
            }
        }
        __syncwarp();

        if (valid) {
            const float* hrow = hsm[w];
            float acc0 = 0.f, acc1 = 0.f;
#pragma unroll 8
            for (int dd = 0; dd < 64; ++dd) {
                float hv = hrow[dd];
                float2 wv = *reinterpret_cast<const float2*>(&Wsm[dd * 66 + lane * 2]);
                acc0 += hv * wv.x;
                acc1 += hv * wv.y;
            }
            *reinterpret_cast<float2*>(out + (size_t)gw * OUTD + lane * 2) = make_float2(acc0, acc1);
        }
        __syncwarp();
    }
}

// ---------------- launch ----------------
extern "C" void kernel_launch(void* const* d_in, const int* in_sizes, int n_in,
                              void* d_out, int out_size) {
    const float* x     = (const float*)d_in[0];
    const int*   ei    = (const int*)  d_in[1];
    const float* Wq    = (const float*)d_in[2];
    const float* bq    = (const float*)d_in[3];
    const float* Wk    = (const float*)d_in[4];
    const float* bk    = (const float*)d_in[5];
    const float* Wv    = (const float*)d_in[6];
    const float* bv    = (const float*)d_in[7];
    const float* Wskip = (const float*)d_in[8];
    const float* bskip = (const float*)d_in[9];
    const float* Wmlp  = (const float*)d_in[10];
    float* out = (float*)d_out;

    int N = in_sizes[0] / INDIM;
    int E = in_sizes[1] / 2;

    static cudaStream_t s2 = nullptr;
    static cudaEvent_t evFork = nullptr, evJoin = nullptr;
    if (s2 == nullptr) {
        cudaStreamCreateWithFlags(&s2, cudaStreamNonBlocking);
        cudaEventCreateWithFlags(&evFork, cudaEventDisableTiming);
        cudaEventCreateWithFlags(&evJoin, cudaEventDisableTiming);
    }
    cudaFuncSetAttribute(gemm_mma_kernel, cudaFuncAttributeMaxDynamicSharedMemorySize,
                         GEMM_SMEM_BYTES);

    // fork: CSR chain + sigma on s2; prep + GEMM on default stream
    cudaEventRecord(evFork, 0);
    cudaStreamWaitEvent(s2, evFork, 0);

    int nblk = (N + 255) / 256;
    zero_kernel<<<(N + 255) / 256, 256, 0, s2>>>(N);
    hist_kernel<<<(E + 255) / 256, 256, 0, s2>>>(ei, E);
    scan_part1<<<nblk, 256, 0, s2>>>(N);
    scan_part2<<<1, 256, 0, s2>>>(nblk, N);
    scan_part3<<<nblk, 256, 0, s2>>>(N);
    scatter_edges_kernel<<<(E + 255) / 256, 256, 0, s2>>>(ei, E);
    sigma_kernel<<<1, 32, 0, s2>>>(Wmlp);
    cudaEventRecord(evJoin, s2);

    dim3 pgrid(COLS_ALL / 32, INDIM / 32);
    dim3 pblock(32, 8);
    prep_kernel<<<pgrid, pblock>>>(Wq, bq, Wk, bk, Wv, bv, Wskip, bskip);
    int mblocks = (N + 127) / 128;
    gemm_mma_kernel<<<mblocks, 256, GEMM_SMEM_BYTES>>>(x, N);

    // join, then fused attention + epilogue + MLP
    cudaStreamWaitEvent(0, evJoin, 0);
    int ngroups = (N + 7) / 8;
    int ablocks = ngroups < 1184 ? ngroups : 1184;
    attn_kernel<<<ablocks, 256>>>(out, N, ngroups);
}

// round 17
// speedup vs baseline: 1.0489x; 1.0489x over previous
#include <cuda_runtime.h>
#include <cuda_fp16.h>
#include <math.h>
#include <stdint.h>

// Problem constants
#define NMAX 50000
#define EMAX 300000
#define INDIM 128
#define HID 64
#define HEADS 4
#define QKVDIM 256
#define COLS_ALL 832    // Wq|Wk|Wv|Wskip
#define OUTD 64
#define NTILES 13

// ---------------- scratch ----------------
__device__ float g_ball[COLS_ALL];
__device__ __align__(16) __half g_Wt_h[COLS_ALL * INDIM];      // [n][k] fp16
__device__ __align__(16) __half g_qh[(size_t)NMAX * QKVDIM];   // q fp16
__device__ __align__(16) __half g_kvh[(size_t)NMAX * 512];     // k[256] | v[256] fp16
__device__ __align__(16) __half g_skiph[(size_t)NMAX * HID];   // skip fp16
__device__ float g_Wms[HID * OUTD];
__device__ int g_deg[NMAX];
__device__ int g_cursor[NMAX];
__device__ int g_rowstart[NMAX + 1];
__device__ int g_esrc[EMAX];
__device__ int g_bsum[4096];

// ---------------- helpers ----------------
__device__ __forceinline__ uint32_t smem_u32(const void* p) {
    uint32_t a;
    asm("{ .reg .u64 t; cvta.to.shared.u64 t, %1; cvt.u32.u64 %0, t; }" : "=r"(a) : "l"(p));
    return a;
}

#define LDMX4(r0, r1, r2, r3, addr) \
    asm volatile("ldmatrix.sync.aligned.m8n8.x4.shared.b16 {%0,%1,%2,%3}, [%4];" \
                 : "=r"(r0), "=r"(r1), "=r"(r2), "=r"(r3) : "r"(addr))

#define MMA16816H(d, a, b0, b1) \
    asm volatile("mma.sync.aligned.m16n8k16.row.col.f32.f16.f16.f32 " \
                 "{%0,%1,%2,%3},{%4,%5,%6,%7},{%8,%9},{%0,%1,%2,%3};" \
                 : "+f"((d)[0]), "+f"((d)[1]), "+f"((d)[2]), "+f"((d)[3]) \
                 : "r"((a)[0]), "r"((a)[1]), "r"((a)[2]), "r"((a)[3]), "r"(b0), "r"(b1))

#define CP_ASYNC16(smaddr, gptr) \
    asm volatile("cp.async.ca.shared.global [%0], [%1], 16;" \
                 :: "r"(smaddr), "l"(gptr) : "memory")
#define CP_ASYNC_COMMIT() asm volatile("cp.async.commit_group;" ::: "memory")
#define CP_ASYNC_WAIT0()  asm volatile("cp.async.wait_group 0;" ::: "memory")

__device__ __forceinline__ uint32_t h2u(__half2 h) { return *reinterpret_cast<uint32_t*>(&h); }

// ---------------- prep: coalesced tiled transpose W -> g_Wt_h (fp16) + biases ----------------
__global__ void prep_kernel(const float* __restrict__ Wq, const float* __restrict__ bq,
                            const float* __restrict__ Wk, const float* __restrict__ bk,
                            const float* __restrict__ Wv, const float* __restrict__ bv,
                            const float* __restrict__ Ws, const float* __restrict__ bs) {
    __shared__ __half tile[32][33];
    int n0 = blockIdx.x * 32;
    int k0 = blockIdx.y * 32;
    int tx = threadIdx.x, ty = threadIdx.y;

#pragma unroll
    for (int r = ty; r < 32; r += 8) {
        int k = k0 + r;
        int n = n0 + tx;
        float w = (n < 256) ? Wq[k * 256 + n]
                : (n < 512) ? Wk[k * 256 + (n - 256)]
                : (n < 768) ? Wv[k * 256 + (n - 512)]
                :             Ws[k * 64  + (n - 768)];
        tile[r][tx] = __float2half_rn(w);
    }
    if (blockIdx.y == 0 && ty == 0) {
        int n = n0 + tx;
        g_ball[n] = (n < 256) ? bq[n] : (n < 512) ? bk[n - 256]
                  : (n < 768) ? bv[n - 512] : bs[n - 768];
    }
    __syncthreads();
#pragma unroll
    for (int r = ty; r < 32; r += 8) {
        int n = n0 + r;
        int k = k0 + tx;
        g_Wt_h[(size_t)n * INDIM + k] = tile[tx][r];
    }
}

// ---------------- spectral norm power iteration (warp-level) ----------------
__global__ void sigma_kernel(const float* __restrict__ Wmlp) {
    __shared__ float Wsh[64 * 65];
    __shared__ float ush[64], vsh[64];
    int t = threadIdx.x;  // 32 threads
    for (int i = t; i < 4096; i += 32) {
        int r = i >> 6, c = i & 63;
        Wsh[r * 65 + c] = Wmlp[i];
    }
    ush[t] = 0.125f; ush[t + 32] = 0.125f;
    __syncwarp();
    float up0 = 0.f, up1 = 0.f;
    for (int it = 0; it < 20; ++it) {
        float s0 = 0.f, s1 = 0.f;
        for (int i = 0; i < 64; ++i) {
            float ui = ush[i];
            s0 += Wsh[i * 65 + t] * ui;
            s1 += Wsh[i * 65 + t + 32] * ui;
        }
        float nn = s0 * s0 + s1 * s1;
#pragma unroll
        for (int o = 16; o > 0; o >>= 1) nn += __shfl_xor_sync(0xFFFFFFFFu, nn, o);
        float inv = 1.f / (sqrtf(nn) + 1e-12f);
        vsh[t] = s0 * inv; vsh[t + 32] = s1 * inv;
        __syncwarp();
        float r0 = 0.f, r1 = 0.f;
        for (int j = 0; j < 64; ++j) {
            float vj = vsh[j];
            r0 += Wsh[t * 65 + j] * vj;
            r1 += Wsh[(t + 32) * 65 + j] * vj;
        }
        up0 = r0; up1 = r1;
        float nu = r0 * r0 + r1 * r1;
#pragma unroll
        for (int o = 16; o > 0; o >>= 1) nu += __shfl_xor_sync(0xFFFFFFFFu, nu, o);
        float invu = 1.f / (sqrtf(nu) + 1e-12f);
        ush[t] = r0 * invu; ush[t + 32] = r1 * invu;
        __syncwarp();
    }
    float sg = ush[t] * up0 + ush[t + 32] * up1;
#pragma unroll
    for (int o = 16; o > 0; o >>= 1) sg += __shfl_xor_sync(0xFFFFFFFFu, sg, o);
    float rinv = 1.f / sg;
    for (int i = t; i < 4096; i += 32) {
        int r = i >> 6, c = i & 63;
        g_Wms[i] = Wsh[r * 65 + c] * rinv;
    }
}

// ---------------- CSR build ----------------
__global__ void zero_kernel(int n) {
    int i = blockIdx.x * blockDim.x + threadIdx.x;
    if (i < n) { g_deg[i] = 0; g_cursor[i] = 0; }
}
__global__ void hist_kernel(const int* __restrict__ ei, int E) {
    int e = blockIdx.x * blockDim.x + threadIdx.x;
    if (e < E) atomicAdd(&g_deg[ei[E + e]], 1);
}
__global__ void scan_part1(int n) {
    __shared__ int s[256];
    int t = threadIdx.x;
    int i = blockIdx.x * 256 + t;
    s[t] = (i < n) ? g_deg[i] : 0;
    __syncthreads();
#pragma unroll
    for (int o = 128; o > 0; o >>= 1) {
        if (t < o) s[t] += s[t + o];
        __syncthreads();
    }
    if (t == 0) g_bsum[blockIdx.x] = s[0];
}
__global__ void scan_part2(int nblk, int n) {
    __shared__ int s[256];
    int t = threadIdx.x;
    s[t] = (t < nblk) ? g_bsum[t] : 0;
    __syncthreads();
#pragma unroll
    for (int o = 1; o < 256; o <<= 1) {
        int v = (t >= o) ? s[t - o] : 0;
        __syncthreads();
        s[t] += v;
        __syncthreads();
    }
    if (t < nblk) g_bsum[t] = (t == 0) ? 0 : s[t - 1];
    if (t == nblk - 1) g_rowstart[n] = s[t];
}
__global__ void scan_part3(int n) {
    __shared__ int s[256];
    int t = threadIdx.x;
    int i = blockIdx.x * 256 + t;
    int v = (i < n) ? g_deg[i] : 0;
    s[t] = v;
    __syncthreads();
#pragma unroll
    for (int o = 1; o < 256; o <<= 1) {
        int u = (t >= o) ? s[t - o] : 0;
        __syncthreads();
        s[t] += u;
        __syncthreads();
    }
    if (i < n) g_rowstart[i] = g_bsum[blockIdx.x] + s[t] - v;
}
__global__ void scatter_edges_kernel(const int* __restrict__ ei, int E) {
    int e = blockIdx.x * blockDim.x + threadIdx.x;
    if (e >= E) return;
    int dst = ei[E + e];
    int pos = g_rowstart[dst] + atomicAdd(&g_cursor[dst], 1);
    g_esrc[pos] = ei[e];
}

// ---------------- fp16 single-pass mma.sync projection GEMM (R15 config + cp.async B fill) ----
// smem: A (128x128 fp16, padded) + B (64x128 fp16) = 51 KB -> 4 CTAs/SM.
#define LDA_B 272
#define SM_A 0
#define SM_B 34816
#define GEMM_SMEM_BYTES 52224

__global__ void __launch_bounds__(256, 4) gemm_mma_kernel(const float* __restrict__ x, int nrows) {
    extern __shared__ __align__(16) char sm[];
    const uint32_t s_base = smem_u32(sm);

    int tid = threadIdx.x;
    int lane = tid & 31;
    int wid = tid >> 5;
    int wm = wid & 3;
    int wn = wid >> 2;
    int row0 = blockIdx.x * 128;

    // ---- A fill: fp32 -> fp16 (once) ----
    {
#pragma unroll
        for (int p = 0; p < 16; ++p) {
            int idx = tid + p * 256;
            int row = idx >> 5;
            int c4 = idx & 31;
            int gr = row0 + row;
            float4 v = make_float4(0.f, 0.f, 0.f, 0.f);
            if (gr < nrows) v = *reinterpret_cast<const float4*>(x + (size_t)gr * INDIM + c4 * 4);
            uint32_t hp0 = h2u(__floats2half2_rn(v.x, v.y));
            uint32_t hp1 = h2u(__floats2half2_rn(v.z, v.w));
            uint32_t off = (uint32_t)row * LDA_B + (uint32_t)c4 * 8;
            *reinterpret_cast<uint2*>(sm + SM_A + off) = make_uint2(hp0, hp1);
        }
    }

    int ar = lane & 15, ac8 = lane >> 4;
    int bg = lane >> 3;
    int bn = ((bg >> 1) << 3) + (lane & 7);
    int bk8 = bg & 1;
    uint32_t a_lane_off = (uint32_t)(wm * 32 + ar) * LDA_B + (uint32_t)ac8 * 16;
    uint32_t b_lane_off = (uint32_t)(wn * 32 + bn) * LDA_B + (uint32_t)bk8 * 16;

    for (int nb = 0; nb < NTILES; ++nb) {
        int col0 = nb * 64;
        int sel = nb >> 2;                       // 0=q 1=k 2=v 3=skip
        __syncthreads();
        // ---- B fill via cp.async (no register round-trip; LSU-issue only) ----
#pragma unroll
        for (int p = 0; p < 4; ++p) {
            int idx = tid + p * 256;
            int row = idx >> 4;
            int c8 = idx & 15;
            const void* gp = (const void*)&g_Wt_h[(size_t)(col0 + row) * INDIM + c8 * 8];
            uint32_t smaddr = s_base + SM_B + (uint32_t)row * LDA_B + (uint32_t)c8 * 16;
            CP_ASYNC16(smaddr, gp);
        }
        CP_ASYNC_COMMIT();
        CP_ASYNC_WAIT0();
        __syncthreads();

        float acc[2][4][4];
#pragma unroll
        for (int mb = 0; mb < 2; ++mb)
#pragma unroll
            for (int jn = 0; jn < 4; ++jn)
#pragma unroll
                for (int r = 0; r < 4; ++r) acc[mb][jn][r] = 0.f;

#pragma unroll 2
        for (int kk = 0; kk < 8; ++kk) {
            uint32_t kbyte = (uint32_t)kk * 32;
            uint32_t ah[8], bb[8];
            uint32_t aaddr0 = s_base + SM_A + a_lane_off + kbyte;
            LDMX4(ah[0], ah[1], ah[2], ah[3], aaddr0);
            LDMX4(ah[4], ah[5], ah[6], ah[7], aaddr0 + 16 * LDA_B);
            uint32_t baddr0 = s_base + SM_B + b_lane_off + kbyte;
            LDMX4(bb[0], bb[1], bb[2], bb[3], baddr0);
            LDMX4(bb[4], bb[5], bb[6], bb[7], baddr0 + 16 * LDA_B);
#pragma unroll
            for (int mb = 0; mb < 2; ++mb) {
#pragma unroll
                for (int jn = 0; jn < 4; ++jn) {
                    MMA16816H(acc[mb][jn], &ah[mb * 4], bb[jn * 2], bb[jn * 2 + 1]);
                }
            }
        }

        int g = lane >> 2, t2 = (lane & 3) * 2;
#pragma unroll
        for (int mb = 0; mb < 2; ++mb) {
            int gr0 = row0 + wm * 32 + mb * 16 + g;
#pragma unroll
            for (int jn = 0; jn < 4; ++jn) {
                int gc = col0 + wn * 32 + jn * 8 + t2;
                float b0 = g_ball[gc], b1 = g_ball[gc + 1];
                float v00 = acc[mb][jn][0] + b0, v01 = acc[mb][jn][1] + b1;
                float v10 = acc[mb][jn][2] + b0, v11 = acc[mb][jn][3] + b1;
                if (sel == 0) {
                    if (gr0 < nrows)
                        *reinterpret_cast<__half2*>(&g_qh[(size_t)gr0 * QKVDIM + gc]) = __floats2half2_rn(v00, v01);
                    if (gr0 + 8 < nrows)
                        *reinterpret_cast<__half2*>(&g_qh[(size_t)(gr0 + 8) * QKVDIM + gc]) = __floats2half2_rn(v10, v11);
                } else if (sel == 3) {
                    int sc = gc - 768;
                    if (gr0 < nrows)
                        *reinterpret_cast<__half2*>(&g_skiph[(size_t)gr0 * HID + sc]) = __floats2half2_rn(v00, v01);
                    if (gr0 + 8 < nrows)
                        *reinterpret_cast<__half2*>(&g_skiph[(size_t)(gr0 + 8) * HID + sc]) = __floats2half2_rn(v10, v11);
                } else {
                    int koff = gc - 256;   // k: [0,256)  v: [256,512)
                    if (gr0 < nrows)
                        *reinterpret_cast<__half2*>(&g_kvh[(size_t)gr0 * 512 + koff]) = __floats2half2_rn(v00, v01);
                    if (gr0 + 8 < nrows)
                        *reinterpret_cast<__half2*>(&g_kvh[(size_t)(gr0 + 8) * 512 + koff]) = __floats2half2_rn(v10, v11);
                }
            }
        }
    }
}

// ---------------- fused attention + head mean + skip + tanh + MLP ----------------
// Warp per node; predicated 4-edge batches + next-batch index prefetch.
__global__ void __launch_bounds__(256) attn_kernel(float* __restrict__ out, int n, int ngroups) {
    __shared__ float Wsm[64 * 66];
    __shared__ float hsm[8][64];
    int tid = threadIdx.x;
    int lane = tid & 31;
    int w = tid >> 5;

    for (int i = tid; i < 4096; i += 256) Wsm[(i >> 6) * 66 + (i & 63)] = g_Wms[i];
    __syncthreads();

    for (int grp = blockIdx.x; grp < ngroups; grp += gridDim.x) {
        int gw = grp * 8 + w;
        bool valid = gw < n;

        if (valid) {
            uint4 qv = *reinterpret_cast<const uint4*>(g_qh + (size_t)gw * QKVDIM + lane * 8);
            float2 q0 = __half22float2(*reinterpret_cast<__half2*>(&qv.x));
            float2 q1 = __half22float2(*reinterpret_cast<__half2*>(&qv.y));
            float2 q2 = __half22float2(*reinterpret_cast<__half2*>(&qv.z));
            float2 q3 = __half22float2(*reinterpret_cast<__half2*>(&qv.w));

            int start = g_rowstart[gw], end = g_rowstart[gw + 1];
            float S[8] = {0.f, 0.f, 0.f, 0.f, 0.f, 0.f, 0.f, 0.f};
            float d = 0.f;

            // prefetch first batch's indices
            int idxN[4];
            if (start < end) {
                int rem0 = end - start;
#pragma unroll
                for (int i = 0; i < 4; ++i) idxN[i] = g_esrc[(i < rem0) ? (start + i) : start];
            }

            for (int p = start; p < end; p += 4) {
                int rem = end - p;  // >= 1
                int idx[4];
#pragma unroll
                for (int i = 0; i < 4; ++i) idx[i] = idxN[i];
                int pn = p + 4;
                if (pn < end) {
                    int remn = end - pn;
#pragma unroll
                    for (int i = 0; i < 4; ++i) idxN[i] = g_esrc[(i < remn) ? (pn + i) : pn];
                }

                uint4 kk[4], vv[4];
#pragma unroll
                for (int i = 0; i < 4; ++i) {
                    const uint4* kv = reinterpret_cast<const uint4*>(g_kvh + (size_t)idx[i] * 512);
                    kk[i] = kv[lane];
                    vv[i] = kv[lane + 32];
                }
                float t[4];
#pragma unroll
                for (int i = 0; i < 4; ++i) {
                    float2 k0 = __half22float2(*reinterpret_cast<__half2*>(&kk[i].x));
                    float2 k1 = __half22float2(*reinterpret_cast<__half2*>(&kk[i].y));
                    float2 k2 = __half22float2(*reinterpret_cast<__half2*>(&kk[i].z));
                    float2 k3 = __half22float2(*reinterpret_cast<__half2*>(&kk[i].w));
                    t[i] = q0.x * k0.x + q0.y * k0.y + q1.x * k1.x + q1.y * k1.y
                         + q2.x * k2.x + q2.y * k2.y + q3.x * k3.x + q3.y * k3.y;
                }
#pragma unroll
                for (int i = 0; i < 4; ++i) t[i] += __shfl_xor_sync(0xFFFFFFFFu, t[i], 1);
#pragma unroll
                for (int i = 0; i < 4; ++i) t[i] += __shfl_xor_sync(0xFFFFFFFFu, t[i], 2);
#pragma unroll
                for (int i = 0; i < 4; ++i) t[i] += __shfl_xor_sync(0xFFFFFFFFu, t[i], 4);
                float e[4];
#pragma unroll
                for (int i = 0; i < 4; ++i) {
                    e[i] = (i < rem) ? __expf(t[i] * 0.125f) : 0.f;
                    d += e[i];
                }
#pragma unroll
                for (int i = 0; i < 4; ++i) {
                    float2 v0 = __half22float2(*reinterpret_cast<__half2*>(&vv[i].x));
                    float2 v1 = __half22float2(*reinterpret_cast<__half2*>(&vv[i].y));
                    float2 v2 = __half22float2(*reinterpret_cast<__half2*>(&vv[i].z));
                    float2 v3 = __half22float2(*reinterpret_cast<__half2*>(&vv[i].w));
                    S[0] += e[i] * v0.x; S[1] += e[i] * v0.y;
                    S[2] += e[i] * v1.x; S[3] += e[i] * v1.y;
                    S[4] += e[i] * v2.x; S[5] += e[i] * v2.y;
                    S[6] += e[i] * v3.x; S[7] += e[i] * v3.y;
                }
            }

            float r = 1.f / (d + 1e-16f);
#pragma unroll
            for (int j = 0; j < 8; ++j) {
                float s = S[j] * r;
                s += __shfl_xor_sync(0xFFFFFFFFu, s, 8);
                s += __shfl_xor_sync(0xFFFFFFFFu, s, 16);
                S[j] = s;
            }

            if (lane < 8) {
                const __half* sk = g_skiph + (size_t)gw * HID + lane * 8;
#pragma unroll
                for (int j = 0; j < 8; ++j)
                    hsm[w][lane * 8 + j] = tanhf(0.25f * S[j] + __half2float(sk[j]));
            }
        }
        __syncwarp();

        if (valid) {
            const float* hrow = hsm[w];
            float acc0 = 0.f, acc1 = 0.f;
#pragma unroll 8
            for (int dd = 0; dd < 64; ++dd) {
                float hv = hrow[dd];
                float2 wv = *reinterpret_cast<const float2*>(&Wsm[dd * 66 + lane * 2]);
                acc0 += hv * wv.x;
                acc1 += hv * wv.y;
            }
            *reinterpret_cast<float2*>(out + (size_t)gw * OUTD + lane * 2) = make_float2(acc0, acc1);
        }
        __syncwarp();
    }
}

// ---------------- launch ----------------
extern "C" void kernel_launch(void* const* d_in, const int* in_sizes, int n_in,
                              void* d_out, int out_size) {
    const float* x     = (const float*)d_in[0];
    const int*   ei    = (const int*)  d_in[1];
    const float* Wq    = (const float*)d_in[2];
    const float* bq    = (const float*)d_in[3];
    const float* Wk    = (const float*)d_in[4];
    const float* bk    = (const float*)d_in[5];
    const float* Wv    = (const float*)d_in[6];
    const float* bv    = (const float*)d_in[7];
    const float* Wskip = (const float*)d_in[8];
    const float* bskip = (const float*)d_in[9];
    const float* Wmlp  = (const float*)d_in[10];
    float* out = (float*)d_out;

    int N = in_sizes[0] / INDIM;
    int E = in_sizes[1] / 2;

    static cudaStream_t s2 = nullptr;
    static cudaEvent_t evFork = nullptr, evJoin = nullptr;
    if (s2 == nullptr) {
        cudaStreamCreateWithFlags(&s2, cudaStreamNonBlocking);
        cudaEventCreateWithFlags(&evFork, cudaEventDisableTiming);
        cudaEventCreateWithFlags(&evJoin, cudaEventDisableTiming);
    }
    cudaFuncSetAttribute(gemm_mma_kernel, cudaFuncAttributeMaxDynamicSharedMemorySize,
                         GEMM_SMEM_BYTES);

    // fork: CSR chain + sigma on s2; prep + GEMM on default stream
    cudaEventRecord(evFork, 0);
    cudaStreamWaitEvent(s2, evFork, 0);

    int nblk = (N + 255) / 256;
    zero_kernel<<<(N + 255) / 256, 256, 0, s2>>>(N);
    hist_kernel<<<(E + 255) / 256, 256, 0, s2>>>(ei, E);
    scan_part1<<<nblk, 256, 0, s2>>>(N);
    scan_part2<<<1, 256, 0, s2>>>(nblk, N);
    scan_part3<<<nblk, 256, 0, s2>>>(N);
    scatter_edges_kernel<<<(E + 255) / 256, 256, 0, s2>>>(ei, E);
    sigma_kernel<<<1, 32, 0, s2>>>(Wmlp);
    cudaEventRecord(evJoin, s2);

    dim3 pgrid(COLS_ALL / 32, INDIM / 32);
    dim3 pblock(32, 8);
    prep_kernel<<<pgrid, pblock>>>(Wq, bq, Wk, bk, Wv, bv, Wskip, bskip);
    int mblocks = (N + 127) / 128;
    gemm_mma_kernel<<<mblocks, 256, GEMM_SMEM_BYTES>>>(x, N);

    // join, then fused attention + epilogue + MLP
    cudaStreamWaitEvent(0, evJoin, 0);
    int ngroups = (N + 7) / 8;
    int ablocks = ngroups < 1184 ? ngroups : 1184;
    attn_kernel<<<ablocks, 256>>>(out, N, ngroups);
}